// round 6
// baseline (speedup 1.0000x reference)
#include <cuda_runtime.h>
#include <stdint.h>
#include <math.h>

#define BATCH 2
#define TSEQ  2048
#define NHEAD 12
#define HDIM  64
#define CEMB  768
#define C3    (3 * CEMB)

__device__ float g_qkv[BATCH * TSEQ * C3];    // 36 MB (tf32-rounded values)
__device__ float g_y[BATCH * TSEQ * CEMB];    // 12 MB (tf32-rounded values)
__device__ float g_xr[BATCH * TSEQ * CEMB];   // rounded x
__device__ float g_war[CEMB * C3];            // rounded W_attn
__device__ float g_wpr[CEMB * CEMB];          // rounded W_proj

__device__ __forceinline__ uint32_t f2tf(float x) {
  uint32_t r;
  asm("cvt.rna.tf32.f32 %0, %1;" : "=r"(r) : "f"(x));
  return r;
}
__device__ __forceinline__ float4 tf4(float4 v) {
  v.x = __uint_as_float(f2tf(v.x));
  v.y = __uint_as_float(f2tf(v.y));
  v.z = __uint_as_float(f2tf(v.z));
  v.w = __uint_as_float(f2tf(v.w));
  return v;
}
__device__ __forceinline__ uint32_t fu(float x) { return __float_as_uint(x); }

__device__ __forceinline__ void mma8(float* c, uint32_t a0, uint32_t a1,
                                     uint32_t a2, uint32_t a3,
                                     uint32_t b0, uint32_t b1) {
  asm volatile(
      "mma.sync.aligned.m16n8k8.row.col.f32.tf32.tf32.f32 "
      "{%0,%1,%2,%3}, {%4,%5,%6,%7}, {%8,%9}, {%0,%1,%2,%3};\n"
      : "+f"(c[0]), "+f"(c[1]), "+f"(c[2]), "+f"(c[3])
      : "r"(a0), "r"(a1), "r"(a2), "r"(a3), "r"(b0), "r"(b1));
}

__device__ __forceinline__ void cpa16(void* s, const void* g) {
  uint32_t sa = (uint32_t)__cvta_generic_to_shared(s);
  asm volatile("cp.async.cg.shared.global [%0], [%1], 16;\n" ::"r"(sa), "l"(g));
}
#define CP_COMMIT() asm volatile("cp.async.commit_group;\n")
#define CP_WAIT(n)  asm volatile("cp.async.wait_group %0;\n" ::"n"(n))

// ---------------------------------------------------------------------------
// Elementwise rna-round to tf32 pre-pass
// ---------------------------------------------------------------------------
__global__ __launch_bounds__(256) void round_tf32(const float* __restrict__ in,
                                                  float* __restrict__ out,
                                                  int n4) {
  int i = blockIdx.x * 256 + threadIdx.x;
  if (i < n4) *(float4*)&out[i * 4] = tf4(*(const float4*)&in[i * 4]);
}

// ---------------------------------------------------------------------------
// tf32 GEMM, 3-stage cp.async, BK=32 (one barrier per 64 MMA/warp).
// 128x128 tile, 256 threads, warp tile 64x32. Operands pre-rounded.
// ---------------------------------------------------------------------------
#define APITCH 36    // 144B row = 9x16B; frag banks (4r+q)&31 unique
#define BPITCH 132   // 528B row
#define ABUF (128 * APITCH)
#define BBUF (32 * BPITCH)
#define GSTAGES 3
#define GEMM_SMEM (GSTAGES * (ABUF + BBUF) * sizeof(float))

template <bool ROUND_OUT>
__global__ __launch_bounds__(256, 2) void gemm_tf32(
    const float* __restrict__ A, const float* __restrict__ B,
    const float* __restrict__ bias, float* __restrict__ C, int N, int K) {
  extern __shared__ float sm[];
  float* As = sm;
  float* Bs = sm + GSTAGES * ABUF;

  const int tid = threadIdx.x;
  const int warp = tid >> 5, lane = tid & 31;
  const int r = lane >> 2, q = lane & 3;
  const int wm = (warp >> 2) * 64, wn = (warp & 3) * 32;
  const int bm = blockIdx.y * 128, bn = blockIdx.x * 128;

  // A: rows ar0, ar0+64; two float4 each at ac, ac+4 (32-col tile)
  const int ar0 = tid >> 2, ac = (tid & 3) * 8;
  // B: rows br0+{0,8,16,24}; one float4 at bc (128-col tile)
  const int br0 = tid >> 5, bc = (tid & 31) * 4;
  const float* Ag = A + (size_t)(bm + ar0) * K + ac;
  const float* Bg = B + (size_t)br0 * N + bn + bc;

  float acc[4][4][4];
#pragma unroll
  for (int i = 0; i < 4; i++)
#pragma unroll
    for (int j = 0; j < 4; j++)
#pragma unroll
      for (int t = 0; t < 4; t++) acc[i][j][t] = 0.0f;

  const int nk = K / 32;

#pragma unroll
  for (int i = 0; i < GSTAGES - 1; i++) {
    if (i < nk) {
      float* Ad = As + i * ABUF;
      float* Bd = Bs + i * BBUF;
      const float* Agk = Ag + i * 32;
      const float* Bgk = Bg + (size_t)i * 32 * N;
      cpa16(&Ad[ar0 * APITCH + ac], Agk);
      cpa16(&Ad[ar0 * APITCH + ac + 4], Agk + 4);
      cpa16(&Ad[(ar0 + 64) * APITCH + ac], Agk + (size_t)64 * K);
      cpa16(&Ad[(ar0 + 64) * APITCH + ac + 4], Agk + (size_t)64 * K + 4);
      cpa16(&Bd[br0 * BPITCH + bc], Bgk);
      cpa16(&Bd[(br0 + 8) * BPITCH + bc], Bgk + (size_t)8 * N);
      cpa16(&Bd[(br0 + 16) * BPITCH + bc], Bgk + (size_t)16 * N);
      cpa16(&Bd[(br0 + 24) * BPITCH + bc], Bgk + (size_t)24 * N);
    }
    CP_COMMIT();
  }
  CP_WAIT(1);
  __syncthreads();

  for (int kb = 0; kb < nk; kb++) {
    const int st = kb % GSTAGES;
    const float* Ac = As + st * ABUF;
    const float* Bc = Bs + st * BBUF;
#pragma unroll
    for (int ks = 0; ks < 4; ks++) {
      const int k0 = ks * 8;
      uint32_t af[4][4];
#pragma unroll
      for (int mt = 0; mt < 4; mt++) {
        const float* ap = &Ac[(wm + mt * 16) * APITCH + k0];
        af[mt][0] = fu(ap[r * APITCH + q]);
        af[mt][1] = fu(ap[(r + 8) * APITCH + q]);
        af[mt][2] = fu(ap[r * APITCH + q + 4]);
        af[mt][3] = fu(ap[(r + 8) * APITCH + q + 4]);
      }
#pragma unroll
      for (int nt = 0; nt < 4; nt++) {
        uint32_t b0 = fu(Bc[(k0 + q) * BPITCH + wn + nt * 8 + r]);
        uint32_t b1 = fu(Bc[(k0 + q + 4) * BPITCH + wn + nt * 8 + r]);
#pragma unroll
        for (int mt = 0; mt < 4; mt++)
          mma8(acc[mt][nt], af[mt][0], af[mt][1], af[mt][2], af[mt][3], b0, b1);
      }
    }

    if (kb + 2 < nk) {
      int sn = (kb + 2) % GSTAGES;
      float* Ad = As + sn * ABUF;
      float* Bd = Bs + sn * BBUF;
      const float* Agk = Ag + (kb + 2) * 32;
      const float* Bgk = Bg + (size_t)(kb + 2) * 32 * N;
      cpa16(&Ad[ar0 * APITCH + ac], Agk);
      cpa16(&Ad[ar0 * APITCH + ac + 4], Agk + 4);
      cpa16(&Ad[(ar0 + 64) * APITCH + ac], Agk + (size_t)64 * K);
      cpa16(&Ad[(ar0 + 64) * APITCH + ac + 4], Agk + (size_t)64 * K + 4);
      cpa16(&Bd[br0 * BPITCH + bc], Bgk);
      cpa16(&Bd[(br0 + 8) * BPITCH + bc], Bgk + (size_t)8 * N);
      cpa16(&Bd[(br0 + 16) * BPITCH + bc], Bgk + (size_t)16 * N);
      cpa16(&Bd[(br0 + 24) * BPITCH + bc], Bgk + (size_t)24 * N);
    }
    CP_COMMIT();
    CP_WAIT(1);
    __syncthreads();
  }

#pragma unroll
  for (int mt = 0; mt < 4; mt++) {
    int row_lo = bm + wm + mt * 16 + r;
#pragma unroll
    for (int nt = 0; nt < 4; nt++) {
      int col = bn + wn + nt * 8 + 2 * q;
      float2 bv = *(const float2*)&bias[col];
      float2 o0 = make_float2(acc[mt][nt][0] + bv.x, acc[mt][nt][1] + bv.y);
      float2 o1 = make_float2(acc[mt][nt][2] + bv.x, acc[mt][nt][3] + bv.y);
      if (ROUND_OUT) {
        o0.x = __uint_as_float(f2tf(o0.x));
        o0.y = __uint_as_float(f2tf(o0.y));
        o1.x = __uint_as_float(f2tf(o1.x));
        o1.y = __uint_as_float(f2tf(o1.y));
      }
      *(float2*)&C[(size_t)row_lo * N + col] = o0;
      *(float2*)&C[(size_t)(row_lo + 8) * N + col] = o1;
    }
  }
}

// ---------------------------------------------------------------------------
// Flash attention, tf32 mma. CTA = 128 queries of one (b,h), 8 warps (256 t).
// Bk=64. K double-buffered via cp.async, V single-buffered. Each K/V tile now
// serves 128 queries (half the global traffic and barriers per unit work).
// ---------------------------------------------------------------------------
#define PITCH 68
// K0(64) + K1(64) + V(64) + P(128) rows
#define ATT_SMEM ((64 * 3 + 128) * PITCH * sizeof(float))  // 87040 B

__global__ __launch_bounds__(256, 2) void attn_tf32() {
  extern __shared__ float sm[];
  float* Kb0 = sm;
  float* Kb1 = sm + 64 * PITCH;
  float* Vs  = sm + 128 * PITCH;
  float* Ps  = sm + 192 * PITCH;   // Q staging, then P (128 rows)

  const int tid = threadIdx.x;
  const int warp = tid >> 5, lane = tid & 31;
  const int r = lane >> 2, q = lane & 3;
  const int qb = 15 - blockIdx.x;      // heavy tiles first
  const int bh = blockIdx.y;
  const int b = bh / NHEAD, h = bh % NHEAD;
  const int q0 = qb * 128;
  const float* qkv = g_qkv + (size_t)b * TSEQ * C3 + h * HDIM;

  const int rbase = tid >> 4;          // 0..15
  const int d4 = (tid & 15) << 2;

  // Stage Q (scale 1/8 exact on tf32 values) into Ps (128 rows)
#pragma unroll
  for (int j = 0; j < 8; j++) {
    int rr = rbase + j * 16;
    float4 v = *(const float4*)&qkv[(size_t)(q0 + rr) * C3 + d4];
    v.x *= 0.125f; v.y *= 0.125f; v.z *= 0.125f; v.w *= 0.125f;
    *(float4*)&Ps[rr * PITCH + d4] = v;
  }
  // prologue: K tile 0
  {
    const float* kg = &qkv[(size_t)rbase * C3 + CEMB + d4];
#pragma unroll
    for (int j = 0; j < 4; j++)
      cpa16(&Kb0[(rbase + j * 16) * PITCH + d4], kg + (size_t)j * 16 * C3);
    CP_COMMIT();
  }
  __syncthreads();

  uint32_t qf[8][4];
  const int wr = warp * 16;
#pragma unroll
  for (int ks = 0; ks < 8; ks++) {
    const float* ap = &Ps[wr * PITCH + ks * 8];
    qf[ks][0] = fu(ap[r * PITCH + q]);
    qf[ks][1] = fu(ap[(r + 8) * PITCH + q]);
    qf[ks][2] = fu(ap[r * PITCH + q + 4]);
    qf[ks][3] = fu(ap[(r + 8) * PITCH + q + 4]);
  }
  __syncthreads();  // qf reads done before Ps reused for P

  float m_lo = -1e30f, m_hi = -1e30f, l_lo = 0.0f, l_hi = 0.0f;
  float o[8][4];
#pragma unroll
  for (int nt = 0; nt < 8; nt++)
#pragma unroll
    for (int t = 0; t < 4; t++) o[nt][t] = 0.0f;

  const int nkt = 2 * qb + 2;  // k tiles covering rows q0..q0+127

  for (int kb = 0; kb < nkt; kb++) {
    {
      const float* vg = &qkv[(size_t)(kb * 64 + rbase) * C3 + 2 * CEMB + d4];
#pragma unroll
      for (int j = 0; j < 4; j++)
        cpa16(&Vs[(rbase + j * 16) * PITCH + d4], vg + (size_t)j * 16 * C3);
      CP_COMMIT();
    }
    if (kb + 1 < nkt) {
      float* Kn = (kb & 1) ? Kb0 : Kb1;
      const float* kg = &qkv[(size_t)((kb + 1) * 64 + rbase) * C3 + CEMB + d4];
#pragma unroll
      for (int j = 0; j < 4; j++)
        cpa16(&Kn[(rbase + j * 16) * PITCH + d4], kg + (size_t)j * 16 * C3);
    }
    CP_COMMIT();

    CP_WAIT(2);       // K(kb) arrived
    __syncthreads();

    const float* Kc = (kb & 1) ? Kb1 : Kb0;

    // S = Q K^T  (16 rows x 64 keys per warp)
    float s[8][4];
#pragma unroll
    for (int nt = 0; nt < 8; nt++)
#pragma unroll
      for (int t = 0; t < 4; t++) s[nt][t] = 0.0f;
#pragma unroll
    for (int ks = 0; ks < 8; ks++) {
#pragma unroll
      for (int nt = 0; nt < 8; nt++) {
        uint32_t b0 = fu(Kc[(nt * 8 + r) * PITCH + ks * 8 + q]);
        uint32_t b1 = fu(Kc[(nt * 8 + r) * PITCH + ks * 8 + q + 4]);
        mma8(s[nt], qf[ks][0], qf[ks][1], qf[ks][2], qf[ks][3], b0, b1);
      }
    }

    // causal mask (global coords); active only near the diagonal of this warp
    if (kb * 64 + 63 > q0 + wr) {
      const int row_lo = q0 + wr + r, row_hi = row_lo + 8;
      const int cb = kb * 64 + 2 * q;
#pragma unroll
      for (int nt = 0; nt < 8; nt++) {
        int col = cb + nt * 8;
        if (col > row_lo) s[nt][0] = -1e30f;
        if (col + 1 > row_lo) s[nt][1] = -1e30f;
        if (col > row_hi) s[nt][2] = -1e30f;
        if (col + 1 > row_hi) s[nt][3] = -1e30f;
      }
    }

    float mx_lo = s[0][0], mx_hi = s[0][2];
#pragma unroll
    for (int nt = 0; nt < 8; nt++) {
      mx_lo = fmaxf(mx_lo, fmaxf(s[nt][0], s[nt][1]));
      mx_hi = fmaxf(mx_hi, fmaxf(s[nt][2], s[nt][3]));
    }
    mx_lo = fmaxf(mx_lo, __shfl_xor_sync(0xffffffffu, mx_lo, 1));
    mx_lo = fmaxf(mx_lo, __shfl_xor_sync(0xffffffffu, mx_lo, 2));
    mx_hi = fmaxf(mx_hi, __shfl_xor_sync(0xffffffffu, mx_hi, 1));
    mx_hi = fmaxf(mx_hi, __shfl_xor_sync(0xffffffffu, mx_hi, 2));

    float mn_lo = fmaxf(m_lo, mx_lo), mn_hi = fmaxf(m_hi, mx_hi);
    float corr_lo = __expf(m_lo - mn_lo), corr_hi = __expf(m_hi - mn_hi);

    float ls_lo = 0.0f, ls_hi = 0.0f;
#pragma unroll
    for (int nt = 0; nt < 8; nt++) {
      int col = nt * 8 + 2 * q;
      float p0 = __uint_as_float(f2tf(__expf(s[nt][0] - mn_lo)));
      float p1 = __uint_as_float(f2tf(__expf(s[nt][1] - mn_lo)));
      float p2 = __uint_as_float(f2tf(__expf(s[nt][2] - mn_hi)));
      float p3 = __uint_as_float(f2tf(__expf(s[nt][3] - mn_hi)));
      ls_lo += p0 + p1;
      ls_hi += p2 + p3;
      *(float2*)&Ps[(wr + r) * PITCH + col] = make_float2(p0, p1);
      *(float2*)&Ps[(wr + r + 8) * PITCH + col] = make_float2(p2, p3);
    }
    ls_lo += __shfl_xor_sync(0xffffffffu, ls_lo, 1);
    ls_lo += __shfl_xor_sync(0xffffffffu, ls_lo, 2);
    ls_hi += __shfl_xor_sync(0xffffffffu, ls_hi, 1);
    ls_hi += __shfl_xor_sync(0xffffffffu, ls_hi, 2);
    l_lo = l_lo * corr_lo + ls_lo;
    l_hi = l_hi * corr_hi + ls_hi;
    m_lo = mn_lo;
    m_hi = mn_hi;

#pragma unroll
    for (int nt = 0; nt < 8; nt++) {
      o[nt][0] *= corr_lo;
      o[nt][1] *= corr_lo;
      o[nt][2] *= corr_hi;
      o[nt][3] *= corr_hi;
    }

    CP_WAIT(1);       // V(kb) arrived
    __syncthreads();

    // O += P V
#pragma unroll
    for (int ks = 0; ks < 8; ks++) {
      uint32_t a0 = fu(Ps[(wr + r) * PITCH + ks * 8 + q]);
      uint32_t a1 = fu(Ps[(wr + r + 8) * PITCH + ks * 8 + q]);
      uint32_t a2 = fu(Ps[(wr + r) * PITCH + ks * 8 + q + 4]);
      uint32_t a3 = fu(Ps[(wr + r + 8) * PITCH + ks * 8 + q + 4]);
#pragma unroll
      for (int nt = 0; nt < 8; nt++) {
        uint32_t b0 = fu(Vs[(ks * 8 + q) * PITCH + nt * 8 + r]);
        uint32_t b1 = fu(Vs[(ks * 8 + q + 4) * PITCH + nt * 8 + r]);
        mma8(o[nt], a0, a1, a2, a3, b0, b1);
      }
    }
    __syncthreads();  // PV readers done before next iter's V overwrite
  }

  const float il_lo = 1.0f / l_lo, il_hi = 1.0f / l_hi;
  const size_t base = ((size_t)(b * TSEQ) + q0 + wr + r) * CEMB + h * HDIM;
#pragma unroll
  for (int nt = 0; nt < 8; nt++) {
    int col = nt * 8 + 2 * q;
    float2 y0 = make_float2(o[nt][0] * il_lo, o[nt][1] * il_lo);
    float2 y1 = make_float2(o[nt][2] * il_hi, o[nt][3] * il_hi);
    y0.x = __uint_as_float(f2tf(y0.x));
    y0.y = __uint_as_float(f2tf(y0.y));
    y1.x = __uint_as_float(f2tf(y1.x));
    y1.y = __uint_as_float(f2tf(y1.y));
    *(float2*)&g_y[base + col] = y0;
    *(float2*)&g_y[base + 8 * CEMB + col] = y1;
  }
}

// ---------------------------------------------------------------------------
extern "C" void kernel_launch(void* const* d_in, const int* in_sizes, int n_in,
                              void* d_out, int out_size) {
  const float* x      = (const float*)d_in[0];
  const float* W_attn = (const float*)d_in[1];
  const float* b_attn = (const float*)d_in[2];
  const float* W_proj = (const float*)d_in[3];
  const float* b_proj = (const float*)d_in[4];
  float* out = (float*)d_out;

  float* qkv; cudaGetSymbolAddress((void**)&qkv, g_qkv);
  float* y;   cudaGetSymbolAddress((void**)&y,   g_y);
  float* xr;  cudaGetSymbolAddress((void**)&xr,  g_xr);
  float* war; cudaGetSymbolAddress((void**)&war, g_war);
  float* wpr; cudaGetSymbolAddress((void**)&wpr, g_wpr);

  const int M = BATCH * TSEQ;  // 4096

  cudaFuncSetAttribute(gemm_tf32<true>,
                       cudaFuncAttributeMaxDynamicSharedMemorySize,
                       (int)GEMM_SMEM);
  cudaFuncSetAttribute(gemm_tf32<false>,
                       cudaFuncAttributeMaxDynamicSharedMemorySize,
                       (int)GEMM_SMEM);
  cudaFuncSetAttribute(attn_tf32, cudaFuncAttributeMaxDynamicSharedMemorySize,
                       (int)ATT_SMEM);

  {
    int n4;
    n4 = (M * CEMB) / 4;
    round_tf32<<<(n4 + 255) / 256, 256>>>(x, xr, n4);
    n4 = (CEMB * C3) / 4;
    round_tf32<<<(n4 + 255) / 256, 256>>>(W_attn, war, n4);
    n4 = (CEMB * CEMB) / 4;
    round_tf32<<<(n4 + 255) / 256, 256>>>(W_proj, wpr, n4);
  }

  gemm_tf32<true><<<dim3(C3 / 128, M / 128), 256, GEMM_SMEM>>>(
      xr, war, b_attn, qkv, C3, CEMB);

  attn_tf32<<<dim3(TSEQ / 128, BATCH * NHEAD), 256, ATT_SMEM>>>();

  gemm_tf32<false><<<dim3(CEMB / 128, M / 128), 256, GEMM_SMEM>>>(
      y, wpr, b_proj, out, CEMB, CEMB);
}

// round 8
// speedup vs baseline: 1.3085x; 1.3085x over previous
#include <cuda_runtime.h>
#include <stdint.h>
#include <math.h>

#define BATCH 2
#define TSEQ  2048
#define NHEAD 12
#define HDIM  64
#define CEMB  768
#define C3    (3 * CEMB)

__device__ float g_qkv[BATCH * TSEQ * C3];    // 36 MB (tf32-rounded values)
__device__ float g_y[BATCH * TSEQ * CEMB];    // 12 MB (tf32-rounded values)
__device__ float g_xr[BATCH * TSEQ * CEMB];   // rounded x
__device__ float g_war[CEMB * C3];            // rounded W_attn
__device__ float g_wpr[CEMB * CEMB];          // rounded W_proj

__device__ __forceinline__ uint32_t f2tf(float x) {
  uint32_t r;
  asm("cvt.rna.tf32.f32 %0, %1;" : "=r"(r) : "f"(x));
  return r;
}
__device__ __forceinline__ float4 tf4(float4 v) {
  v.x = __uint_as_float(f2tf(v.x));
  v.y = __uint_as_float(f2tf(v.y));
  v.z = __uint_as_float(f2tf(v.z));
  v.w = __uint_as_float(f2tf(v.w));
  return v;
}
__device__ __forceinline__ uint32_t fu(float x) { return __float_as_uint(x); }

__device__ __forceinline__ void mma8(float* c, uint32_t a0, uint32_t a1,
                                     uint32_t a2, uint32_t a3,
                                     uint32_t b0, uint32_t b1) {
  asm volatile(
      "mma.sync.aligned.m16n8k8.row.col.f32.tf32.tf32.f32 "
      "{%0,%1,%2,%3}, {%4,%5,%6,%7}, {%8,%9}, {%0,%1,%2,%3};\n"
      : "+f"(c[0]), "+f"(c[1]), "+f"(c[2]), "+f"(c[3])
      : "r"(a0), "r"(a1), "r"(a2), "r"(a3), "r"(b0), "r"(b1));
}

__device__ __forceinline__ void cpa16(void* s, const void* g) {
  uint32_t sa = (uint32_t)__cvta_generic_to_shared(s);
  asm volatile("cp.async.cg.shared.global [%0], [%1], 16;\n" ::"r"(sa), "l"(g));
}
#define CP_COMMIT() asm volatile("cp.async.commit_group;\n")
#define CP_WAIT(n)  asm volatile("cp.async.wait_group %0;\n" ::"n"(n))

// ---------------------------------------------------------------------------
// Elementwise rna-round to tf32 pre-pass
// ---------------------------------------------------------------------------
__global__ __launch_bounds__(256) void round_tf32(const float* __restrict__ in,
                                                  float* __restrict__ out,
                                                  int n4) {
  int i = blockIdx.x * 256 + threadIdx.x;
  if (i < n4) *(float4*)&out[i * 4] = tf4(*(const float4*)&in[i * 4]);
}

// ---------------------------------------------------------------------------
// tf32 GEMM, 4-stage cp.async pipeline (R5 structure). 128x128 tile, BK=16,
// 256 threads, warp tile 64x32. Operands pre-rounded -> no CVT in hot loop.
// BPITCH=136 (== 8 mod 32): B-frag banks (8q+r) are conflict-free.
// ---------------------------------------------------------------------------
#define APITCH 20    // A-frag banks (20r+q) mod 32 all unique
#define BPITCH 136   // 544B row = 34x16B; B-frag banks (8q+r) all unique
#define ABUF (128 * APITCH)
#define BBUF (16 * BPITCH)
#define GSTAGES 4
#define GEMM_SMEM (GSTAGES * (ABUF + BBUF) * sizeof(float))

template <bool ROUND_OUT>
__global__ __launch_bounds__(256, 2) void gemm_tf32(
    const float* __restrict__ A, const float* __restrict__ B,
    const float* __restrict__ bias, float* __restrict__ C, int N, int K) {
  extern __shared__ float sm[];
  float* As = sm;
  float* Bs = sm + GSTAGES * ABUF;

  const int tid = threadIdx.x;
  const int warp = tid >> 5, lane = tid & 31;
  const int r = lane >> 2, q = lane & 3;
  const int wm = (warp >> 2) * 64, wn = (warp & 3) * 32;
  const int bm = blockIdx.y * 128, bn = blockIdx.x * 128;

  const int ar0 = tid >> 2, ac = (tid & 3) * 4;
  const int br0 = tid >> 5, bc = (tid & 31) * 4;
  const float* Ag = A + (size_t)(bm + ar0) * K + ac;
  const float* Bg = B + (size_t)br0 * N + bn + bc;

  float acc[4][4][4];
#pragma unroll
  for (int i = 0; i < 4; i++)
#pragma unroll
    for (int j = 0; j < 4; j++)
#pragma unroll
      for (int t = 0; t < 4; t++) acc[i][j][t] = 0.0f;

  const int nk = K / 16;

#pragma unroll
  for (int i = 0; i < GSTAGES - 1; i++) {
    if (i < nk) {
      float* Ad = As + i * ABUF;
      float* Bd = Bs + i * BBUF;
      const float* Agk = Ag + i * 16;
      const float* Bgk = Bg + (size_t)i * 16 * N;
      cpa16(&Ad[ar0 * APITCH + ac], Agk);
      cpa16(&Ad[(ar0 + 64) * APITCH + ac], Agk + (size_t)64 * K);
      cpa16(&Bd[br0 * BPITCH + bc], Bgk);
      cpa16(&Bd[(br0 + 8) * BPITCH + bc], Bgk + (size_t)8 * N);
    }
    CP_COMMIT();
  }
  CP_WAIT(2);
  __syncthreads();

  for (int kb = 0; kb < nk; kb++) {
    const float* Ac = As + (kb & 3) * ABUF;
    const float* Bc = Bs + (kb & 3) * BBUF;
#pragma unroll
    for (int ks = 0; ks < 2; ks++) {
      const int k0 = ks * 8;
      uint32_t af[4][4];
#pragma unroll
      for (int mt = 0; mt < 4; mt++) {
        const float* ap = &Ac[(wm + mt * 16) * APITCH + k0];
        af[mt][0] = fu(ap[r * APITCH + q]);
        af[mt][1] = fu(ap[(r + 8) * APITCH + q]);
        af[mt][2] = fu(ap[r * APITCH + q + 4]);
        af[mt][3] = fu(ap[(r + 8) * APITCH + q + 4]);
      }
#pragma unroll
      for (int nt = 0; nt < 4; nt++) {
        uint32_t b0 = fu(Bc[(k0 + q) * BPITCH + wn + nt * 8 + r]);
        uint32_t b1 = fu(Bc[(k0 + q + 4) * BPITCH + wn + nt * 8 + r]);
#pragma unroll
        for (int mt = 0; mt < 4; mt++)
          mma8(acc[mt][nt], af[mt][0], af[mt][1], af[mt][2], af[mt][3], b0, b1);
      }
    }

    if (kb + 3 < nk) {
      int st = (kb + 3) & 3;
      float* Ad = As + st * ABUF;
      float* Bd = Bs + st * BBUF;
      const float* Agk = Ag + (kb + 3) * 16;
      const float* Bgk = Bg + (size_t)(kb + 3) * 16 * N;
      cpa16(&Ad[ar0 * APITCH + ac], Agk);
      cpa16(&Ad[(ar0 + 64) * APITCH + ac], Agk + (size_t)64 * K);
      cpa16(&Bd[br0 * BPITCH + bc], Bgk);
      cpa16(&Bd[(br0 + 8) * BPITCH + bc], Bgk + (size_t)8 * N);
    }
    CP_COMMIT();
    CP_WAIT(2);
    __syncthreads();
  }

#pragma unroll
  for (int mt = 0; mt < 4; mt++) {
    int row_lo = bm + wm + mt * 16 + r;
#pragma unroll
    for (int nt = 0; nt < 4; nt++) {
      int col = bn + wn + nt * 8 + 2 * q;
      float2 bv = *(const float2*)&bias[col];
      float2 o0 = make_float2(acc[mt][nt][0] + bv.x, acc[mt][nt][1] + bv.y);
      float2 o1 = make_float2(acc[mt][nt][2] + bv.x, acc[mt][nt][3] + bv.y);
      if (ROUND_OUT) {
        o0.x = __uint_as_float(f2tf(o0.x));
        o0.y = __uint_as_float(f2tf(o0.y));
        o1.x = __uint_as_float(f2tf(o1.x));
        o1.y = __uint_as_float(f2tf(o1.y));
      }
      *(float2*)&C[(size_t)row_lo * N + col] = o0;
      *(float2*)&C[(size_t)(row_lo + 8) * N + col] = o1;
    }
  }
}

// ---------------------------------------------------------------------------
// Flash attention (R5 structure: 64q/CTA, 4 warps, 3 CTAs/SM, K double-buf,
// V single-buf). VPITCH=72 (== 8 mod 32): PV b-frag banks (8q+r) unique.
// K/P keep PITCH=68 (== 4 mod 32): their frag banks (4r+q) unique.
// ---------------------------------------------------------------------------
#define PITCH 68
#define VPITCH 72
// layout: K0(64xPITCH), K1(64xPITCH), V(64xVPITCH), P(64xPITCH)
#define VS_OFF (2 * 64 * PITCH)
#define PS_OFF (VS_OFF + 64 * VPITCH)
#define ATT_SMEM ((PS_OFF + 64 * PITCH) * sizeof(float))  // 70656 B

__global__ __launch_bounds__(128, 3) void attn_tf32() {
  extern __shared__ float sm[];
  float* Kb0 = sm;
  float* Kb1 = sm + 64 * PITCH;
  float* Vs  = sm + VS_OFF;
  float* Ps  = sm + PS_OFF;

  const int tid = threadIdx.x;
  const int warp = tid >> 5, lane = tid & 31;
  const int r = lane >> 2, q = lane & 3;
  const int qb = 31 - blockIdx.x;  // heavy tiles first
  const int bh = blockIdx.y;
  const int b = bh / NHEAD, h = bh % NHEAD;
  const int q0 = qb * 64;
  const float* qkv = g_qkv + (size_t)b * TSEQ * C3 + h * HDIM;

  const int rbase = tid >> 4;
  const int d4 = (tid & 15) << 2;

  // Stage Q (scale by 1/8 exact on tf32 values) into Ps
#pragma unroll
  for (int j = 0; j < 8; j++) {
    int rr = rbase + j * 8;
    float4 v = *(const float4*)&qkv[(size_t)(q0 + rr) * C3 + d4];
    v.x *= 0.125f; v.y *= 0.125f; v.z *= 0.125f; v.w *= 0.125f;
    *(float4*)&Ps[rr * PITCH + d4] = v;
  }
  {
    const float* kg = &qkv[(size_t)rbase * C3 + CEMB + d4];
#pragma unroll
    for (int j = 0; j < 8; j++)
      cpa16(&Kb0[(rbase + j * 8) * PITCH + d4], kg + (size_t)j * 8 * C3);
    CP_COMMIT();
  }
  __syncthreads();

  uint32_t qf[8][4];
  const int wr = warp * 16;
#pragma unroll
  for (int ks = 0; ks < 8; ks++) {
    const float* ap = &Ps[wr * PITCH + ks * 8];
    qf[ks][0] = fu(ap[r * PITCH + q]);
    qf[ks][1] = fu(ap[(r + 8) * PITCH + q]);
    qf[ks][2] = fu(ap[r * PITCH + q + 4]);
    qf[ks][3] = fu(ap[(r + 8) * PITCH + q + 4]);
  }
  __syncthreads();

  float m_lo = -1e30f, m_hi = -1e30f, l_lo = 0.0f, l_hi = 0.0f;
  float o[8][4];
#pragma unroll
  for (int nt = 0; nt < 8; nt++)
#pragma unroll
    for (int t = 0; t < 4; t++) o[nt][t] = 0.0f;

  for (int kb = 0; kb <= qb; kb++) {
    {
      const float* vg = &qkv[(size_t)(kb * 64 + rbase) * C3 + 2 * CEMB + d4];
#pragma unroll
      for (int j = 0; j < 8; j++)
        cpa16(&Vs[(rbase + j * 8) * VPITCH + d4], vg + (size_t)j * 8 * C3);
      CP_COMMIT();
    }
    if (kb < qb) {
      float* Kn = (kb & 1) ? Kb0 : Kb1;
      const float* kg = &qkv[(size_t)((kb + 1) * 64 + rbase) * C3 + CEMB + d4];
#pragma unroll
      for (int j = 0; j < 8; j++)
        cpa16(&Kn[(rbase + j * 8) * PITCH + d4], kg + (size_t)j * 8 * C3);
    }
    CP_COMMIT();

    CP_WAIT(2);
    __syncthreads();

    const float* Kc = (kb & 1) ? Kb1 : Kb0;

    float s[8][4];
#pragma unroll
    for (int nt = 0; nt < 8; nt++)
#pragma unroll
      for (int t = 0; t < 4; t++) s[nt][t] = 0.0f;
#pragma unroll
    for (int ks = 0; ks < 8; ks++) {
#pragma unroll
      for (int nt = 0; nt < 8; nt++) {
        uint32_t b0 = fu(Kc[(nt * 8 + r) * PITCH + ks * 8 + q]);
        uint32_t b1 = fu(Kc[(nt * 8 + r) * PITCH + ks * 8 + q + 4]);
        mma8(s[nt], qf[ks][0], qf[ks][1], qf[ks][2], qf[ks][3], b0, b1);
      }
    }

    if (kb == qb) {
      const int row_lo = wr + r, row_hi = row_lo + 8;
#pragma unroll
      for (int nt = 0; nt < 8; nt++) {
        int col = nt * 8 + 2 * q;
        if (col > row_lo) s[nt][0] = -1e30f;
        if (col + 1 > row_lo) s[nt][1] = -1e30f;
        if (col > row_hi) s[nt][2] = -1e30f;
        if (col + 1 > row_hi) s[nt][3] = -1e30f;
      }
    }

    float mx_lo = s[0][0], mx_hi = s[0][2];
#pragma unroll
    for (int nt = 0; nt < 8; nt++) {
      mx_lo = fmaxf(mx_lo, fmaxf(s[nt][0], s[nt][1]));
      mx_hi = fmaxf(mx_hi, fmaxf(s[nt][2], s[nt][3]));
    }
    mx_lo = fmaxf(mx_lo, __shfl_xor_sync(0xffffffffu, mx_lo, 1));
    mx_lo = fmaxf(mx_lo, __shfl_xor_sync(0xffffffffu, mx_lo, 2));
    mx_hi = fmaxf(mx_hi, __shfl_xor_sync(0xffffffffu, mx_hi, 1));
    mx_hi = fmaxf(mx_hi, __shfl_xor_sync(0xffffffffu, mx_hi, 2));

    float mn_lo = fmaxf(m_lo, mx_lo), mn_hi = fmaxf(m_hi, mx_hi);
    float corr_lo = __expf(m_lo - mn_lo), corr_hi = __expf(m_hi - mn_hi);

    float ls_lo = 0.0f, ls_hi = 0.0f;
#pragma unroll
    for (int nt = 0; nt < 8; nt++) {
      int col = nt * 8 + 2 * q;
      float p0 = __uint_as_float(f2tf(__expf(s[nt][0] - mn_lo)));
      float p1 = __uint_as_float(f2tf(__expf(s[nt][1] - mn_lo)));
      float p2 = __uint_as_float(f2tf(__expf(s[nt][2] - mn_hi)));
      float p3 = __uint_as_float(f2tf(__expf(s[nt][3] - mn_hi)));
      ls_lo += p0 + p1;
      ls_hi += p2 + p3;
      *(float2*)&Ps[(wr + r) * PITCH + col] = make_float2(p0, p1);
      *(float2*)&Ps[(wr + r + 8) * PITCH + col] = make_float2(p2, p3);
    }
    ls_lo += __shfl_xor_sync(0xffffffffu, ls_lo, 1);
    ls_lo += __shfl_xor_sync(0xffffffffu, ls_lo, 2);
    ls_hi += __shfl_xor_sync(0xffffffffu, ls_hi, 1);
    ls_hi += __shfl_xor_sync(0xffffffffu, ls_hi, 2);
    l_lo = l_lo * corr_lo + ls_lo;
    l_hi = l_hi * corr_hi + ls_hi;
    m_lo = mn_lo;
    m_hi = mn_hi;

#pragma unroll
    for (int nt = 0; nt < 8; nt++) {
      o[nt][0] *= corr_lo;
      o[nt][1] *= corr_lo;
      o[nt][2] *= corr_hi;
      o[nt][3] *= corr_hi;
    }

    CP_WAIT(1);
    __syncthreads();

    // O += P V  (V frag banks (8q+r): conflict-free with VPITCH=72)
#pragma unroll
    for (int ks = 0; ks < 8; ks++) {
      uint32_t a0 = fu(Ps[(wr + r) * PITCH + ks * 8 + q]);
      uint32_t a1 = fu(Ps[(wr + r + 8) * PITCH + ks * 8 + q]);
      uint32_t a2 = fu(Ps[(wr + r) * PITCH + ks * 8 + q + 4]);
      uint32_t a3 = fu(Ps[(wr + r + 8) * PITCH + ks * 8 + q + 4]);
#pragma unroll
      for (int nt = 0; nt < 8; nt++) {
        uint32_t b0 = fu(Vs[(ks * 8 + q) * VPITCH + nt * 8 + r]);
        uint32_t b1 = fu(Vs[(ks * 8 + q + 4) * VPITCH + nt * 8 + r]);
        mma8(o[nt], a0, a1, a2, a3, b0, b1);
      }
    }
    __syncthreads();
  }

  const float il_lo = 1.0f / l_lo, il_hi = 1.0f / l_hi;
  const size_t base = ((size_t)(b * TSEQ) + q0 + wr + r) * CEMB + h * HDIM;
#pragma unroll
  for (int nt = 0; nt < 8; nt++) {
    int col = nt * 8 + 2 * q;
    float2 y0 = make_float2(o[nt][0] * il_lo, o[nt][1] * il_lo);
    float2 y1 = make_float2(o[nt][2] * il_hi, o[nt][3] * il_hi);
    y0.x = __uint_as_float(f2tf(y0.x));
    y0.y = __uint_as_float(f2tf(y0.y));
    y1.x = __uint_as_float(f2tf(y1.x));
    y1.y = __uint_as_float(f2tf(y1.y));
    *(float2*)&g_y[base + col] = y0;
    *(float2*)&g_y[base + 8 * CEMB + col] = y1;
  }
}

// ---------------------------------------------------------------------------
extern "C" void kernel_launch(void* const* d_in, const int* in_sizes, int n_in,
                              void* d_out, int out_size) {
  const float* x      = (const float*)d_in[0];
  const float* W_attn = (const float*)d_in[1];
  const float* b_attn = (const float*)d_in[2];
  const float* W_proj = (const float*)d_in[3];
  const float* b_proj = (const float*)d_in[4];
  float* out = (float*)d_out;

  float* qkv; cudaGetSymbolAddress((void**)&qkv, g_qkv);
  float* y;   cudaGetSymbolAddress((void**)&y,   g_y);
  float* xr;  cudaGetSymbolAddress((void**)&xr,  g_xr);
  float* war; cudaGetSymbolAddress((void**)&war, g_war);
  float* wpr; cudaGetSymbolAddress((void**)&wpr, g_wpr);

  const int M = BATCH * TSEQ;  // 4096

  cudaFuncSetAttribute(gemm_tf32<true>,
                       cudaFuncAttributeMaxDynamicSharedMemorySize,
                       (int)GEMM_SMEM);
  cudaFuncSetAttribute(gemm_tf32<false>,
                       cudaFuncAttributeMaxDynamicSharedMemorySize,
                       (int)GEMM_SMEM);
  cudaFuncSetAttribute(attn_tf32, cudaFuncAttributeMaxDynamicSharedMemorySize,
                       (int)ATT_SMEM);

  {
    int n4;
    n4 = (M * CEMB) / 4;
    round_tf32<<<(n4 + 255) / 256, 256>>>(x, xr, n4);
    n4 = (CEMB * C3) / 4;
    round_tf32<<<(n4 + 255) / 256, 256>>>(W_attn, war, n4);
    n4 = (CEMB * CEMB) / 4;
    round_tf32<<<(n4 + 255) / 256, 256>>>(W_proj, wpr, n4);
  }

  gemm_tf32<true><<<dim3(C3 / 128, M / 128), 256, GEMM_SMEM>>>(
      xr, war, b_attn, qkv, C3, CEMB);

  attn_tf32<<<dim3(TSEQ / 64, BATCH * NHEAD), 128, ATT_SMEM>>>();

  gemm_tf32<false><<<dim3(CEMB / 128, M / 128), 256, GEMM_SMEM>>>(
      y, wpr, b_proj, out, CEMB, CEMB);
}